// round 10
// baseline (speedup 1.0000x reference)
#include <cuda_runtime.h>
#include <math.h>
#include <float.h>
#include <stdint.h>

// Problem constants
#define Bv   8
#define Lv   4096
#define LP   4097          // L + 1 (bias token)
#define KDv  512
#define EDv  1024
#define DK   64            // KD / H
#define DV   128           // ED / H
#define BH   64            // B * H
#define KCHUNK   (LP * DK)          // floats per (b,h) key chunk in raw view
#define VCHUNK   (LP * DV)          // floats per (b,h) value chunk in raw view
#define KBATCH   (Lv * KDv)         // real key floats per batch
#define VBATCH   (Lv * EDv)         // real value floats per batch
#define KBATCH4  (KBATCH / 4)
#define NT   16                     // j-tiles for the AV kernel
#define TILE 257                    // ceil(4097 / 16)
#define RPB  64                     // k_scores rows per pipeline tile (16KB)
#define NTIL 4                      // tiles per block (double-buffered)
#define RBLK (RPB * NTIL)           // 256 rows per block
#define SBLK 17                     // ceil(4097 / 256) blocks per bh

// Scratch (allocation-free rule: __device__ globals)
__device__ float g_probs[BH * LP];            // unnormalized exp(scores)
__device__ float g_bsum[BH * SBLK];           // per-block partial sum-of-exp
__device__ float g_partial[BH * NT * DV];     // 512 KB AV partials

__device__ __forceinline__ uint32_t smem_u32(const void* p) {
    uint32_t a;
    asm("{ .reg .u64 tmp; cvta.to.shared.u64 tmp, %1; cvt.u32.u64 %0, tmp; }"
        : "=r"(a) : "l"(p));
    return a;
}
__device__ __forceinline__ void cp_async16(uint32_t dst, const void* src) {
    asm volatile("cp.async.cg.shared.global [%0], [%1], 16;"
                 :: "r"(dst), "l"(src) : "memory");
}

// ---------------------------------------------------------------------------
// Kernel 1: p[bh,j] = exp(dot64(Q[h],K[bh,j,:]) * w[h,j] + bias[h,j])
// grid (SBLK, BH), 128 threads. Each block covers 256 rows as 4 tiles of 64,
// double-buffered cp.async pipeline: prefetch tile i+1 while computing tile i.
// ---------------------------------------------------------------------------
__global__ void __launch_bounds__(128) k_scores(
        const float* __restrict__ keys,
        const float* __restrict__ k_bias,
        const float* __restrict__ query,
        const float* __restrict__ sw,
        const float* __restrict__ sb) {
    __shared__ float4 sk[2][RPB * 16];  // 2 x 16 KB, swizzled columns
    __shared__ float4 sq[16];
    __shared__ float  shs[4];

    int bh   = blockIdx.y;
    int b    = bh >> 3;
    int h    = bh & 7;
    int t    = threadIdx.x;
    int base = blockIdx.x * RBLK;

    if (t < 16) sq[t] = *((const float4*)(query + h * DK) + t);

    int fbase4 = (h * KCHUNK) >> 2;     // float4 offset of head chunk
    const float4* kb4 = (const float4*)keys + (size_t)b * KBATCH4;
    const float4* bb4 = (const float4*)k_bias;
    uint32_t sb0 = smem_u32(sk[0]);
    uint32_t sb1 = smem_u32(sk[1]);

    // stage one 64-row tile into the given smem buffer
    auto stage = [&](int tile) {
        uint32_t sbuf = (tile & 1) ? sb1 : sb0;
        int j0   = base + tile * RPB;
        int jmax = j0 + RPB - 1;
        bool fast = (jmax < LP) && (fbase4 + jmax * 16 + 15 < KBATCH4);
        if (fast) {
            const float4* gsrc = kb4 + fbase4 + j0 * 16;
            #pragma unroll
            for (int i = 0; i < 8; i++) {
                int flat = t + i * 128;
                int row  = flat >> 4;
                int c4   = flat & 15;
                int phys = row * 16 + ((c4 + row) & 15);
                cp_async16(sbuf + phys * 16, gsrc + flat);
            }
        } else {
            #pragma unroll
            for (int i = 0; i < 8; i++) {
                int flat = t + i * 128;
                int row  = flat >> 4;
                int c4   = flat & 15;
                int jc   = min(j0 + row, LP - 1);
                int f4   = fbase4 + jc * 16 + c4;
                const float4* src = (f4 >= KBATCH4) ? (bb4 + (f4 - KBATCH4))
                                                    : (kb4 + f4);
                int phys = row * 16 + ((c4 + row) & 15);
                cp_async16(sbuf + phys * 16, src);
            }
        }
        asm volatile("cp.async.commit_group;");
    };

    stage(0);

    int   rrow = t >> 1;            // row within tile (0..63)
    int   half = t & 1;             // which half of the 16 float4s
    float esum = 0.0f;              // per-thread running sum of exps

    #pragma unroll
    for (int tile = 0; tile < NTIL; tile++) {
        if (tile + 1 < NTIL) {
            stage(tile + 1);                        // prefetch next
            asm volatile("cp.async.wait_group 1;"); // current tile done
        } else {
            asm volatile("cp.async.wait_group 0;");
        }
        __syncthreads();

        const float4* buf  = sk[tile & 1];
        const float4* rowp = buf + rrow * 16;
        int j = base + tile * RPB + rrow;

        float a0 = 0.f, a1 = 0.f;
        #pragma unroll
        for (int k = 0; k < 8; k += 2) {
            int i0 = half * 8 + k;
            float4 x0 = rowp[(i0 + rrow) & 15],     q0 = sq[i0];
            float4 x1 = rowp[(i0 + 1 + rrow) & 15], q1 = sq[i0 + 1];
            a0 += x0.x * q0.x + x0.y * q0.y + x0.z * q0.z + x0.w * q0.w;
            a1 += x1.x * q1.x + x1.y * q1.y + x1.z * q1.z + x1.w * q1.w;
        }
        float s = a0 + a1;
        s += __shfl_xor_sync(0xffffffffu, s, 1);    // combine halves
        if (half == 0 && j < LP) {
            int wi = h * LP + j;
            float e = expf(s * __ldg(sw + wi) + __ldg(sb + wi));
            g_probs[bh * LP + j] = e;
            esum += e;
        }
        __syncthreads();            // buffer reuse barrier
    }

    // block sum of exps (deterministic)
    int lane = t & 31, warp = t >> 5;
    float wsum = esum;
    #pragma unroll
    for (int o = 16; o > 0; o >>= 1)
        wsum += __shfl_xor_sync(0xffffffffu, wsum, o);
    if (lane == 0) shs[warp] = wsum;
    __syncthreads();
    if (t == 0)
        g_bsum[bh * SBLK + blockIdx.x] = (shs[0] + shs[1]) + (shs[2] + shs[3]);
}

// ---------------------------------------------------------------------------
// Kernel 2: partial[bh,tile,d] = sum_{j in tile} p[bh,j] * V[bh,j,d]
// grid (NT, BH), 256 threads = 8 warps; warps interleave rows mod 8.
// Unroll x4 with front-batched loads. (Measured ~6.4 TB/s — unchanged.)
// ---------------------------------------------------------------------------
__global__ void k_av(const float* __restrict__ values,
                     const float* __restrict__ v_bias) {
    int tile = blockIdx.x;
    int bh   = blockIdx.y;
    int b = bh >> 3, h = bh & 7;
    int r8 = threadIdx.x >> 5;
    int c  = threadIdx.x & 31;

    const float* p = g_probs + bh * LP;
    int j0 = tile * TILE;
    int j1 = min(j0 + TILE, LP);

    float4 acc = make_float4(0.f, 0.f, 0.f, 0.f);
    int j = j0 + r8;
    for (; j + 24 < j1; j += 32) {
        float p0 = __ldg(p + j);
        float p1 = __ldg(p + j + 8);
        float p2 = __ldg(p + j + 16);
        float p3 = __ldg(p + j + 24);
        int f0 = h * VCHUNK + j * DV;
        int f1 = f0 + 8 * DV, f2 = f0 + 16 * DV, f3 = f0 + 24 * DV;
        const float* r0 = (f0 >= VBATCH) ? (v_bias + (f0 - VBATCH)) : (values + b * VBATCH + f0);
        const float* r1 = (f1 >= VBATCH) ? (v_bias + (f1 - VBATCH)) : (values + b * VBATCH + f1);
        const float* r2 = (f2 >= VBATCH) ? (v_bias + (f2 - VBATCH)) : (values + b * VBATCH + f2);
        const float* r3 = (f3 >= VBATCH) ? (v_bias + (f3 - VBATCH)) : (values + b * VBATCH + f3);
        float4 v0 = __ldcs((const float4*)(r0 + c * 4));
        float4 v1 = __ldcs((const float4*)(r1 + c * 4));
        float4 v2 = __ldcs((const float4*)(r2 + c * 4));
        float4 v3 = __ldcs((const float4*)(r3 + c * 4));
        acc.x += p0 * v0.x + p1 * v1.x + p2 * v2.x + p3 * v3.x;
        acc.y += p0 * v0.y + p1 * v1.y + p2 * v2.y + p3 * v3.y;
        acc.z += p0 * v0.z + p1 * v1.z + p2 * v2.z + p3 * v3.z;
        acc.w += p0 * v0.w + p1 * v1.w + p2 * v2.w + p3 * v3.w;
    }
    for (; j < j1; j += 8) {
        float pa = __ldg(p + j);
        int fa = h * VCHUNK + j * DV;
        const float* ra = (fa >= VBATCH) ? (v_bias + (fa - VBATCH)) : (values + b * VBATCH + fa);
        float4 va = __ldcs((const float4*)(ra + c * 4));
        acc.x += pa * va.x;
        acc.y += pa * va.y;
        acc.z += pa * va.z;
        acc.w += pa * va.w;
    }

    __shared__ float4 red[8][32];
    red[r8][c] = acc;
    __syncthreads();
    if (r8 == 0) {
        float4 a = red[0][c];
        #pragma unroll
        for (int w = 1; w < 8; w++) {
            float4 x = red[w][c];
            a.x += x.x; a.y += x.y; a.z += x.z; a.w += x.w;
        }
        *(float4*)(g_partial + (bh * NT + tile) * DV + c * 4) = a;
    }
}

// ---------------------------------------------------------------------------
// Kernel 3: S[bh] = sum of block sums; reduce NT partials, /S, LayerNorm.
// One block of 256 threads per batch.
// ---------------------------------------------------------------------------
__global__ void k_ln(const float* __restrict__ gamma,
                     const float* __restrict__ beta,
                     float* __restrict__ out) {
    __shared__ float sh_invS[8];
    __shared__ float sh_s[8];
    __shared__ float sh_q[8];
    int b = blockIdx.x;
    int t = threadIdx.x;            // 0..255
    int lane = t & 31, warp = t >> 5;

    // Phase A: per-head sum of exps (warp w -> head w)
    {
        const float* bs = g_bsum + (b * 8 + warp) * SBLK;
        float s = (lane < SBLK) ? bs[lane] : 0.0f;
        #pragma unroll
        for (int o = 16; o > 0; o >>= 1)
            s += __shfl_xor_sync(0xffffffffu, s, o);
        if (lane == 0) sh_invS[warp] = 1.0f / s;
    }
    __syncthreads();

    // Phase B: reduce partials (float4, MLP=NT), normalize, LayerNorm
    int D  = t * 4;
    int hh = t >> 5;
    int dd = D & 127;
    int bh = b * 8 + hh;

    const float* pp = g_partial + bh * (NT * DV) + dd;
    float4 a = make_float4(0.f, 0.f, 0.f, 0.f);
    #pragma unroll
    for (int k = 0; k < NT; k++) {
        float4 x = *(const float4*)(pp + k * DV);
        a.x += x.x; a.y += x.y; a.z += x.z; a.w += x.w;
    }
    float invS = sh_invS[hh];
    a.x *= invS; a.y *= invS; a.z *= invS; a.w *= invS;

    float s = a.x + a.y + a.z + a.w;
    float q = a.x * a.x + a.y * a.y + a.z * a.z + a.w * a.w;
    #pragma unroll
    for (int o = 16; o > 0; o >>= 1) {
        s += __shfl_xor_sync(0xffffffffu, s, o);
        q += __shfl_xor_sync(0xffffffffu, q, o);
    }
    if (lane == 0) { sh_s[warp] = s; sh_q[warp] = q; }
    __syncthreads();
    if (warp == 0 && lane < 8) {
        s = sh_s[lane];
        q = sh_q[lane];
        #pragma unroll
        for (int o = 4; o > 0; o >>= 1) {
            s += __shfl_xor_sync(0x000000ffu, s, o);
            q += __shfl_xor_sync(0x000000ffu, q, o);
        }
        if (lane == 0) { sh_s[0] = s; sh_q[0] = q; }
    }
    __syncthreads();
    float mean = sh_s[0] * (1.0f / EDv);
    float var  = sh_q[0] * (1.0f / EDv) - mean * mean;
    float inv  = rsqrtf(var + 1e-5f);

    float4 gm = *(const float4*)(gamma + D);
    float4 bt = *(const float4*)(beta + D);
    float4 o4;
    o4.x = (a.x - mean) * inv * gm.x + bt.x;
    o4.y = (a.y - mean) * inv * gm.y + bt.y;
    o4.z = (a.z - mean) * inv * gm.z + bt.z;
    o4.w = (a.w - mean) * inv * gm.w + bt.w;
    *(float4*)(out + b * EDv + D) = o4;
}

// ---------------------------------------------------------------------------
// Launch: inputs in metadata order:
// keys, values, query, k_bias, v_bias, softmax_weight, softmax_bias, gamma, beta
// ---------------------------------------------------------------------------
extern "C" void kernel_launch(void* const* d_in, const int* in_sizes, int n_in,
                              void* d_out, int out_size) {
    const float* keys   = (const float*)d_in[0];
    const float* values = (const float*)d_in[1];
    const float* query  = (const float*)d_in[2];
    const float* k_bias = (const float*)d_in[3];
    const float* v_bias = (const float*)d_in[4];
    const float* sw     = (const float*)d_in[5];
    const float* sb     = (const float*)d_in[6];
    const float* gamma  = (const float*)d_in[7];
    const float* beta   = (const float*)d_in[8];
    float* out = (float*)d_out;

    dim3 g1(SBLK, BH);
    k_scores<<<g1, 128>>>(keys, k_bias, query, sw, sb);

    dim3 g2(NT, BH);
    k_av<<<g2, 256>>>(values, v_bias);

    k_ln<<<Bv, 256>>>(gamma, beta, out);
}

// round 11
// speedup vs baseline: 1.0707x; 1.0707x over previous
#include <cuda_runtime.h>
#include <math.h>
#include <float.h>
#include <stdint.h>

// Problem constants
#define Bv   8
#define Lv   4096
#define LP   4097          // L + 1 (bias token)
#define KDv  512
#define EDv  1024
#define DK   64            // KD / H
#define DV   128           // ED / H
#define BH   64            // B * H
#define KCHUNK   (LP * DK)          // floats per (b,h) key chunk in raw view
#define VCHUNK   (LP * DV)          // floats per (b,h) value chunk in raw view
#define KBATCH   (Lv * KDv)         // real key floats per batch
#define VBATCH   (Lv * EDv)         // real value floats per batch
#define NT   16                     // j-tiles
#define TILE 257                    // ceil(4097 / 16)

// Scratch (allocation-free rule: __device__ globals)
__device__ float g_bsum[BH * NT];             // per-(bh,tile) sum of exps
__device__ float g_partial[BH * NT * DV];     // 512 KB partial A vectors

// ---------------------------------------------------------------------------
// Fused kernel: for each (tile, bh), over rows j in tile:
//   s_j = dot64(Q[h], K[bh,j,:]);  e_j = exp(s_j * w[h,j] + b[h,j])
//   acc[0:128] += e_j * V[bh,j,:];  esum += e_j
// Two rows per iteration: lanes 0-15 score row jA, lanes 16-31 row jB=jA+8.
// V rows: full-warp float4 (512B coalesced). No probs materialized.
// ---------------------------------------------------------------------------
__global__ void __launch_bounds__(256) k_fused(
        const float* __restrict__ keys,
        const float* __restrict__ k_bias,
        const float* __restrict__ values,
        const float* __restrict__ v_bias,
        const float* __restrict__ query,
        const float* __restrict__ sw,
        const float* __restrict__ sb) {
    __shared__ float4 sq[16];            // query row (64 floats)
    __shared__ float4 red[8][32];        // cross-warp reduce
    __shared__ float  shs[8];

    int tile = blockIdx.x;
    int bh   = blockIdx.y;
    int b = bh >> 3, h = bh & 7;
    int t    = threadIdx.x;
    int w    = t >> 5;                   // warp 0..7 -> row phase
    int lane = t & 31;
    int half = lane >> 4;                // 0: row jA, 1: row jB
    int li   = lane & 15;                // float4 slot in K row
    int c    = lane;                     // float4 slot in V row

    if (t < 16) sq[t] = *((const float4*)(query + h * DK) + t);
    __syncthreads();

    const float* swh = sw + h * LP;
    const float* sbh = sb + h * LP;
    int kchunk = h * KCHUNK;
    int vchunk = h * VCHUNK;
    const float* kbat = keys   + (size_t)b * KBATCH;
    const float* vbat = values + (size_t)b * VBATCH;

    int j0 = tile * TILE;
    int j1 = min(j0 + TILE, LP);

    float4 acc  = make_float4(0.f, 0.f, 0.f, 0.f);
    float  esum = 0.0f;

    int j = j0 + w;
    // main loop: two rows (j, j+8) per iteration
    for (; j + 8 < j1; j += 16) {
        int jk = j + half * 8;           // row this half-warp scores
        // K row load (256B per half-warp; one LDG covers both rows)
        int fk = kchunk + jk * DK + li * 4;
        const float* kp = (fk >= KBATCH) ? (k_bias + (fk - KBATCH)) : (kbat + fk);
        float4 kv = __ldcs((const float4*)kp);
        float4 qv = sq[li];
        float s = kv.x * qv.x + kv.y * qv.y + kv.z * qv.z + kv.w * qv.w;
        #pragma unroll
        for (int o = 8; o > 0; o >>= 1)
            s += __shfl_xor_sync(0xffffffffu, s, o);
        float e = expf(s * __ldg(swh + jk) + __ldg(sbh + jk));
        float eA = __shfl_sync(0xffffffffu, e, 0);
        float eB = __shfl_sync(0xffffffffu, e, 16);

        // V rows (512B each, full warp)
        int fA = vchunk + j * DV;
        int fB = fA + 8 * DV;
        const float* rA = (fA >= VBATCH) ? (v_bias + (fA - VBATCH)) : (vbat + fA);
        const float* rB = (fB >= VBATCH) ? (v_bias + (fB - VBATCH)) : (vbat + fB);
        float4 vA = __ldcs((const float4*)(rA + c * 4));
        float4 vB = __ldcs((const float4*)(rB + c * 4));
        acc.x += eA * vA.x + eB * vB.x;
        acc.y += eA * vA.y + eB * vB.y;
        acc.z += eA * vA.z + eB * vB.z;
        acc.w += eA * vA.w + eB * vB.w;
        if (lane == 0) esum += eA + eB;
    }
    // tail: single rows
    for (; j < j1; j += 8) {
        int fk = kchunk + j * DK + li * 4;
        const float* kp = (fk >= KBATCH) ? (k_bias + (fk - KBATCH)) : (kbat + fk);
        float4 kv = __ldcs((const float4*)kp);
        float4 qv = sq[li];
        float s = kv.x * qv.x + kv.y * qv.y + kv.z * qv.z + kv.w * qv.w;
        #pragma unroll
        for (int o = 8; o > 0; o >>= 1)
            s += __shfl_xor_sync(0xffffffffu, s, o);
        float e = expf(s * __ldg(swh + j) + __ldg(sbh + j));
        e = __shfl_sync(0xffffffffu, e, 0);

        int fA = vchunk + j * DV;
        const float* rA = (fA >= VBATCH) ? (v_bias + (fA - VBATCH)) : (vbat + fA);
        float4 vA = __ldcs((const float4*)(rA + c * 4));
        acc.x += e * vA.x;
        acc.y += e * vA.y;
        acc.z += e * vA.z;
        acc.w += e * vA.w;
        if (lane == 0) esum += e;
    }

    // cross-warp reduce of acc (8 warps) and esum
    red[w][c] = acc;
    if (lane == 0) shs[w] = esum;
    __syncthreads();
    if (w == 0) {
        float4 a = red[0][c];
        #pragma unroll
        for (int ww = 1; ww < 8; ww++) {
            float4 x = red[ww][c];
            a.x += x.x; a.y += x.y; a.z += x.z; a.w += x.w;
        }
        *(float4*)(g_partial + (bh * NT + tile) * DV + c * 4) = a;
        if (lane == 0) {
            float s = 0.0f;
            #pragma unroll
            for (int ww = 0; ww < 8; ww++) s += shs[ww];
            g_bsum[bh * NT + tile] = s;
        }
    }
}

// ---------------------------------------------------------------------------
// Kernel 2: S[bh] = sum of tile sums; reduce NT partials, /S, LayerNorm.
// One block of 256 threads per batch.
// ---------------------------------------------------------------------------
__global__ void k_ln(const float* __restrict__ gamma,
                     const float* __restrict__ beta,
                     float* __restrict__ out) {
    __shared__ float sh_invS[8];
    __shared__ float sh_s[8];
    __shared__ float sh_q[8];
    int b = blockIdx.x;
    int t = threadIdx.x;            // 0..255
    int lane = t & 31, warp = t >> 5;

    // Phase A: per-head sum of exps (warp w -> head w; NT=16 values)
    {
        const float* bs = g_bsum + (b * 8 + warp) * NT;
        float s = (lane < NT) ? bs[lane] : 0.0f;
        #pragma unroll
        for (int o = 16; o > 0; o >>= 1)
            s += __shfl_xor_sync(0xffffffffu, s, o);
        if (lane == 0) sh_invS[warp] = 1.0f / s;
    }
    __syncthreads();

    // Phase B: reduce partials (float4, MLP=NT), normalize, LayerNorm
    int D  = t * 4;
    int hh = t >> 5;
    int dd = D & 127;
    int bh = b * 8 + hh;

    const float* pp = g_partial + bh * (NT * DV) + dd;
    float4 a = make_float4(0.f, 0.f, 0.f, 0.f);
    #pragma unroll
    for (int k = 0; k < NT; k++) {
        float4 x = *(const float4*)(pp + k * DV);
        a.x += x.x; a.y += x.y; a.z += x.z; a.w += x.w;
    }
    float invS = sh_invS[hh];
    a.x *= invS; a.y *= invS; a.z *= invS; a.w *= invS;

    float s = a.x + a.y + a.z + a.w;
    float q = a.x * a.x + a.y * a.y + a.z * a.z + a.w * a.w;
    #pragma unroll
    for (int o = 16; o > 0; o >>= 1) {
        s += __shfl_xor_sync(0xffffffffu, s, o);
        q += __shfl_xor_sync(0xffffffffu, q, o);
    }
    if (lane == 0) { sh_s[warp] = s; sh_q[warp] = q; }
    __syncthreads();
    if (warp == 0 && lane < 8) {
        s = sh_s[lane];
        q = sh_q[lane];
        #pragma unroll
        for (int o = 4; o > 0; o >>= 1) {
            s += __shfl_xor_sync(0x000000ffu, s, o);
            q += __shfl_xor_sync(0x000000ffu, q, o);
        }
        if (lane == 0) { sh_s[0] = s; sh_q[0] = q; }
    }
    __syncthreads();
    float mean = sh_s[0] * (1.0f / EDv);
    float var  = sh_q[0] * (1.0f / EDv) - mean * mean;
    float inv  = rsqrtf(var + 1e-5f);

    float4 gm = *(const float4*)(gamma + D);
    float4 bt = *(const float4*)(beta + D);
    float4 o4;
    o4.x = (a.x - mean) * inv * gm.x + bt.x;
    o4.y = (a.y - mean) * inv * gm.y + bt.y;
    o4.z = (a.z - mean) * inv * gm.z + bt.z;
    o4.w = (a.w - mean) * inv * gm.w + bt.w;
    *(float4*)(out + b * EDv + D) = o4;
}

// ---------------------------------------------------------------------------
// Launch: inputs in metadata order:
// keys, values, query, k_bias, v_bias, softmax_weight, softmax_bias, gamma, beta
// ---------------------------------------------------------------------------
extern "C" void kernel_launch(void* const* d_in, const int* in_sizes, int n_in,
                              void* d_out, int out_size) {
    const float* keys   = (const float*)d_in[0];
    const float* values = (const float*)d_in[1];
    const float* query  = (const float*)d_in[2];
    const float* k_bias = (const float*)d_in[3];
    const float* v_bias = (const float*)d_in[4];
    const float* sw     = (const float*)d_in[5];
    const float* sb     = (const float*)d_in[6];
    const float* gamma  = (const float*)d_in[7];
    const float* beta   = (const float*)d_in[8];
    float* out = (float*)d_out;

    dim3 g1(NT, BH);
    k_fused<<<g1, 256>>>(keys, k_bias, values, v_bias, query, sw, sb);

    k_ln<<<Bv, 256>>>(gamma, beta, out);
}

// round 12
// speedup vs baseline: 1.0988x; 1.0263x over previous
#include <cuda_runtime.h>
#include <math.h>
#include <float.h>
#include <stdint.h>

// Problem constants
#define Bv   8
#define Lv   4096
#define LP   4097          // L + 1 (bias token)
#define KDv  512
#define EDv  1024
#define DK   64            // KD / H
#define DV   128           // ED / H
#define BH   64            // B * H
#define KCHUNK   (LP * DK)          // floats per (b,h) key chunk in raw view
#define VCHUNK   (LP * DV)          // floats per (b,h) value chunk in raw view
#define KBATCH   (Lv * KDv)         // real key floats per batch
#define VBATCH   (Lv * EDv)         // real value floats per batch
#define NT   16                     // j-tiles
#define TILE 257                    // ceil(4097 / 16)

// Scratch (allocation-free rule: __device__ globals)
__device__ float g_bsum[BH * NT];             // per-(bh,tile) sum of exps
__device__ float g_partial[BH * NT * DV];     // 512 KB partial A vectors

// ---------------------------------------------------------------------------
// Fused kernel: for each (tile, bh), over rows j in tile:
//   s_j = dot64(Q[h], K[bh,j,:]);  e_j = exp(s_j * w[h,j] + b[h,j])
//   acc[0:128] += e_j * V[bh,j,:];  esum += e_j
// 4 rows per iteration: two half-warp K loads (rows j,j+8 then j+16,j+24),
// four front-batched V row loads. No probs materialized.
// ---------------------------------------------------------------------------
__global__ void __launch_bounds__(256) k_fused(
        const float* __restrict__ keys,
        const float* __restrict__ k_bias,
        const float* __restrict__ values,
        const float* __restrict__ v_bias,
        const float* __restrict__ query,
        const float* __restrict__ sw,
        const float* __restrict__ sb) {
    __shared__ float4 sq[16];            // query row (64 floats)
    __shared__ float4 red[8][32];        // cross-warp reduce
    __shared__ float  shs[8];

    int tile = blockIdx.x;
    int bh   = blockIdx.y;
    int b = bh >> 3, h = bh & 7;
    int t    = threadIdx.x;
    int w    = t >> 5;                   // warp 0..7 -> row phase
    int lane = t & 31;
    int half = lane >> 4;                // 0: first row of pair, 1: second
    int li   = lane & 15;                // float4 slot in K row
    int c    = lane;                     // float4 slot in V row

    if (t < 16) sq[t] = *((const float4*)(query + h * DK) + t);
    __syncthreads();

    const float* swh = sw + h * LP;
    const float* sbh = sb + h * LP;
    int kchunk = h * KCHUNK;
    int vchunk = h * VCHUNK;
    const float* kbat = keys   + (size_t)b * KBATCH;
    const float* vbat = values + (size_t)b * VBATCH;

    int j0 = tile * TILE;
    int j1 = min(j0 + TILE, LP);

    float4 acc  = make_float4(0.f, 0.f, 0.f, 0.f);
    float  esum = 0.0f;
    float4 qv   = sq[li];

    int j = j0 + w;
    // main loop: 4 rows (j, j+8, j+16, j+24) per iteration
    for (; j + 24 < j1; j += 32) {
        // --- front-batched K loads: rows (j, j+8) and (j+16, j+24) ---
        int jkA = j + half * 8;
        int jkB = j + 16 + half * 8;
        int fkA = kchunk + jkA * DK + li * 4;
        int fkB = kchunk + jkB * DK + li * 4;
        const float* kpA = (fkA >= KBATCH) ? (k_bias + (fkA - KBATCH)) : (kbat + fkA);
        const float* kpB = (fkB >= KBATCH) ? (k_bias + (fkB - KBATCH)) : (kbat + fkB);
        float4 kvA = __ldcs((const float4*)kpA);
        float4 kvB = __ldcs((const float4*)kpB);

        // --- front-batched V loads: 4 rows ---
        int f0 = vchunk + j * DV;
        int f1 = f0 + 8 * DV, f2 = f0 + 16 * DV, f3 = f0 + 24 * DV;
        const float* r0 = (f0 >= VBATCH) ? (v_bias + (f0 - VBATCH)) : (vbat + f0);
        const float* r1 = (f1 >= VBATCH) ? (v_bias + (f1 - VBATCH)) : (vbat + f1);
        const float* r2 = (f2 >= VBATCH) ? (v_bias + (f2 - VBATCH)) : (vbat + f2);
        const float* r3 = (f3 >= VBATCH) ? (v_bias + (f3 - VBATCH)) : (vbat + f3);
        float4 v0 = __ldcs((const float4*)(r0 + c * 4));
        float4 v1 = __ldcs((const float4*)(r1 + c * 4));
        float4 v2 = __ldcs((const float4*)(r2 + c * 4));
        float4 v3 = __ldcs((const float4*)(r3 + c * 4));

        // --- scores for 4 rows ---
        float sA = kvA.x * qv.x + kvA.y * qv.y + kvA.z * qv.z + kvA.w * qv.w;
        float sB = kvB.x * qv.x + kvB.y * qv.y + kvB.z * qv.z + kvB.w * qv.w;
        #pragma unroll
        for (int o = 8; o > 0; o >>= 1) {
            sA += __shfl_xor_sync(0xffffffffu, sA, o);
            sB += __shfl_xor_sync(0xffffffffu, sB, o);
        }
        float eA2 = expf(sA * __ldg(swh + jkA) + __ldg(sbh + jkA));
        float eB2 = expf(sB * __ldg(swh + jkB) + __ldg(sbh + jkB));
        float e0 = __shfl_sync(0xffffffffu, eA2, 0);
        float e1 = __shfl_sync(0xffffffffu, eA2, 16);
        float e2 = __shfl_sync(0xffffffffu, eB2, 0);
        float e3 = __shfl_sync(0xffffffffu, eB2, 16);

        acc.x += e0 * v0.x + e1 * v1.x + e2 * v2.x + e3 * v3.x;
        acc.y += e0 * v0.y + e1 * v1.y + e2 * v2.y + e3 * v3.y;
        acc.z += e0 * v0.z + e1 * v1.z + e2 * v2.z + e3 * v3.z;
        acc.w += e0 * v0.w + e1 * v1.w + e2 * v2.w + e3 * v3.w;
        if (lane == 0) esum += (e0 + e1) + (e2 + e3);
    }
    // tail: single rows
    for (; j < j1; j += 8) {
        int fk = kchunk + j * DK + li * 4;
        const float* kp = (fk >= KBATCH) ? (k_bias + (fk - KBATCH)) : (kbat + fk);
        float4 kv = __ldcs((const float4*)kp);
        float s = kv.x * qv.x + kv.y * qv.y + kv.z * qv.z + kv.w * qv.w;
        #pragma unroll
        for (int o = 8; o > 0; o >>= 1)
            s += __shfl_xor_sync(0xffffffffu, s, o);
        float e = expf(s * __ldg(swh + j) + __ldg(sbh + j));
        e = __shfl_sync(0xffffffffu, e, 0);

        int fA = vchunk + j * DV;
        const float* rA = (fA >= VBATCH) ? (v_bias + (fA - VBATCH)) : (vbat + fA);
        float4 vA = __ldcs((const float4*)(rA + c * 4));
        acc.x += e * vA.x;
        acc.y += e * vA.y;
        acc.z += e * vA.z;
        acc.w += e * vA.w;
        if (lane == 0) esum += e;
    }

    // allow the dependent k_ln launch to proceed; its griddepsync still
    // waits for this kernel's full completion (and memory visibility).
    cudaTriggerProgrammaticLaunchCompletion();

    // cross-warp reduce of acc (8 warps) and esum
    red[w][c] = acc;
    if (lane == 0) shs[w] = esum;
    __syncthreads();
    if (w == 0) {
        float4 a = red[0][c];
        #pragma unroll
        for (int ww = 1; ww < 8; ww++) {
            float4 x = red[ww][c];
            a.x += x.x; a.y += x.y; a.z += x.z; a.w += x.w;
        }
        *(float4*)(g_partial + (bh * NT + tile) * DV + c * 4) = a;
        if (lane == 0) {
            float s = 0.0f;
            #pragma unroll
            for (int ww = 0; ww < 8; ww++) s += shs[ww];
            g_bsum[bh * NT + tile] = s;
        }
    }
}

// ---------------------------------------------------------------------------
// Kernel 2: S[bh] = sum of tile sums; reduce NT partials, /S, LayerNorm.
// One block of 256 threads per batch. PDL secondary: starts early, syncs.
// ---------------------------------------------------------------------------
__global__ void k_ln(const float* __restrict__ gamma,
                     const float* __restrict__ beta,
                     float* __restrict__ out) {
    __shared__ float sh_invS[8];
    __shared__ float sh_s[8];
    __shared__ float sh_q[8];
    int b = blockIdx.x;
    int t = threadIdx.x;            // 0..255
    int lane = t & 31, warp = t >> 5;

    // prefetch gamma/beta (independent of primary kernel's outputs)
    int D  = t * 4;
    float4 gm = *(const float4*)(gamma + D);
    float4 bt = *(const float4*)(beta + D);

    // wait for k_fused completion + memory visibility
    cudaGridDependencySynchronize();

    // Phase A: per-head sum of exps (warp w -> head w; NT=16 values)
    {
        const float* bs = g_bsum + (b * 8 + warp) * NT;
        float s = (lane < NT) ? bs[lane] : 0.0f;
        #pragma unroll
        for (int o = 16; o > 0; o >>= 1)
            s += __shfl_xor_sync(0xffffffffu, s, o);
        if (lane == 0) sh_invS[warp] = 1.0f / s;
    }
    __syncthreads();

    // Phase B: reduce partials (float4, MLP=NT), normalize, LayerNorm
    int hh = t >> 5;
    int dd = D & 127;
    int bh = b * 8 + hh;

    const float* pp = g_partial + bh * (NT * DV) + dd;
    float4 a = make_float4(0.f, 0.f, 0.f, 0.f);
    #pragma unroll
    for (int k = 0; k < NT; k++) {
        float4 x = *(const float4*)(pp + k * DV);
        a.x += x.x; a.y += x.y; a.z += x.z; a.w += x.w;
    }
    float invS = sh_invS[hh];
    a.x *= invS; a.y *= invS; a.z *= invS; a.w *= invS;

    float s = a.x + a.y + a.z + a.w;
    float q = a.x * a.x + a.y * a.y + a.z * a.z + a.w * a.w;
    #pragma unroll
    for (int o = 16; o > 0; o >>= 1) {
        s += __shfl_xor_sync(0xffffffffu, s, o);
        q += __shfl_xor_sync(0xffffffffu, q, o);
    }
    if (lane == 0) { sh_s[warp] = s; sh_q[warp] = q; }
    __syncthreads();
    if (warp == 0 && lane < 8) {
        s = sh_s[lane];
        q = sh_q[lane];
        #pragma unroll
        for (int o = 4; o > 0; o >>= 1) {
            s += __shfl_xor_sync(0x000000ffu, s, o);
            q += __shfl_xor_sync(0x000000ffu, q, o);
        }
        if (lane == 0) { sh_s[0] = s; sh_q[0] = q; }
    }
    __syncthreads();
    float mean = sh_s[0] * (1.0f / EDv);
    float var  = sh_q[0] * (1.0f / EDv) - mean * mean;
    float inv  = rsqrtf(var + 1e-5f);

    float4 o4;
    o4.x = (a.x - mean) * inv * gm.x + bt.x;
    o4.y = (a.y - mean) * inv * gm.y + bt.y;
    o4.z = (a.z - mean) * inv * gm.z + bt.z;
    o4.w = (a.w - mean) * inv * gm.w + bt.w;
    *(float4*)(out + b * EDv + D) = o4;
}

// ---------------------------------------------------------------------------
// Launch: inputs in metadata order:
// keys, values, query, k_bias, v_bias, softmax_weight, softmax_bias, gamma, beta
// ---------------------------------------------------------------------------
extern "C" void kernel_launch(void* const* d_in, const int* in_sizes, int n_in,
                              void* d_out, int out_size) {
    const float* keys   = (const float*)d_in[0];
    const float* values = (const float*)d_in[1];
    const float* query  = (const float*)d_in[2];
    const float* k_bias = (const float*)d_in[3];
    const float* v_bias = (const float*)d_in[4];
    const float* sw     = (const float*)d_in[5];
    const float* sb     = (const float*)d_in[6];
    const float* gamma  = (const float*)d_in[7];
    const float* beta   = (const float*)d_in[8];
    float* out = (float*)d_out;

    dim3 g1(NT, BH);
    k_fused<<<g1, 256>>>(keys, k_bias, values, v_bias, query, sw, sb);

    // PDL launch of k_ln: overlaps its launch/ramp with k_fused's epilogue
    cudaLaunchConfig_t cfg = {};
    cfg.gridDim  = dim3(Bv);
    cfg.blockDim = dim3(256);
    cfg.dynamicSmemBytes = 0;
    cfg.stream = 0;
    cudaLaunchAttribute attrs[1];
    attrs[0].id = cudaLaunchAttributeProgrammaticStreamSerialization;
    attrs[0].val.programmaticStreamSerializationAllowed = 1;
    cfg.attrs = attrs;
    cfg.numAttrs = 1;
    cudaLaunchKernelEx(&cfg, k_ln, gamma, beta, out);
}